// round 7
// baseline (speedup 1.0000x reference)
#include <cuda_runtime.h>
#include <cuda_bf16.h>

// loss = [pen_neg(v) + (N*sum(r^2) - (sum r)^2)] / (N(N-1)/2) + pen_range(v)
// r_i = haversine(st_i, q) - v*t_i, DEG = 3.14/180 (sic).
//
// Latency-minimal: 1 warp per block, zero shared memory / zero barriers,
// polynomial trig (single MUFU sqrt per station), warp-granular partials,
// last-ticket warp finalizes.

#define MAX_BLOCKS 512

__device__ float2 g_part[MAX_BLOCKS];
__device__ unsigned int g_ticket = 0;

__global__ void __launch_bounds__(32)
find_loc_warp(const float* __restrict__ lat,
              const float* __restrict__ lon,
              const float* __restrict__ v,
              const float* __restrict__ st_lat,
              const float* __restrict__ st_lon,
              const float* __restrict__ times,
              float* __restrict__ out,
              int n, int nblocks)
{
    const float DEG = 3.14f / 180.0f;
    const float R   = 6373.0f;
    const float C16 = 1.0f / 6.0f;

    const float la2 = lat[0] * DEG;
    const float lo2 = lon[0] * DEG;
    const float vv  = v[0];
    const float cos_la2 = __cosf(la2);
    const float sin_la2 = __sinf(la2);

    int lane = threadIdx.x;
    int i = blockIdx.x * 32 + lane;

    float s1 = 0.0f, s2 = 0.0f;
    if (i < n) {
        float la1 = st_lat[i] * DEG;
        float lo1 = st_lon[i] * DEG;
        float dla = la2 - la1;            // |dla| <~ 0.05 rad
        float dlo = lo2 - lo1;

        // sin(x) ~= x - x^3/6 for tiny x (rel err < 1e-8 here)
        float h = 0.5f * dla;
        float sdla = h * (1.0f - h * h * C16);
        float g = 0.5f * dlo;
        float sdlo = g * (1.0f - g * g * C16);

        // cos(la1) = cos(la2 + d), d = la1 - la2 tiny:
        // cos_la2*(1 - d^2/2) - sin_la2*(d - d^3/6)
        float dd = la1 - la2;
        float dd2 = dd * dd;
        float cos_la1 = cos_la2 * (1.0f - 0.5f * dd2)
                      - sin_la2 * (dd * (1.0f - dd2 * C16));

        float a = sdla * sdla + cos_la1 * cos_la2 * (sdlo * sdlo);
        // c = 2*atan2(sqrt(a), sqrt(1-a)) = 2*asin(sqrt(a)); s <= ~0.03
        float s = __fsqrt_rn(a);
        float sq = s * s;
        float asin_s = s * (1.0f + sq * (C16 + sq * (3.0f / 40.0f)));
        float d = (2.0f * R) * asin_s;

        float r = d - vv * times[i];
        s1 = r;
        s2 = r * r;
    }

    // warp reduce
    #pragma unroll
    for (int off = 16; off > 0; off >>= 1) {
        s1 += __shfl_down_sync(0xFFFFFFFFu, s1, off);
        s2 += __shfl_down_sync(0xFFFFFFFFu, s2, off);
    }

    unsigned int tkt = 0;
    if (lane == 0) {
        g_part[blockIdx.x] = make_float2(s1, s2);
        __threadfence();                       // release partial
        tkt = atomicInc(&g_ticket, (unsigned int)(nblocks - 1));
    }
    tkt = __shfl_sync(0xFFFFFFFFu, tkt, 0);
    if (tkt != (unsigned int)(nblocks - 1)) return;

    // Last warp: acquire + reduce all partials.
    __threadfence();
    float a1 = 0.0f, a2 = 0.0f;
    for (int j = lane; j < nblocks; j += 32) {
        float2 p = g_part[j];
        a1 += p.x;
        a2 += p.y;
    }
    #pragma unroll
    for (int off = 16; off > 0; off >>= 1) {
        a1 += __shfl_down_sync(0xFFFFFFFFu, a1, off);
        a2 += __shfl_down_sync(0xFFFFFFFFu, a2, off);
    }

    if (lane == 0) {
        float fn = (float)n;
        // sum_{i<j} (r_j - r_i)^2 = N*sum(r^2) - (sum r)^2
        float pair_sum = fn * a2 - a1 * a1;
        float pen_neg = (vv < 0.0f) ? (-vv * 10.0f) : 0.0f;
        float num = fn * (fn - 1.0f) * 0.5f;
        float loss = (pen_neg + pair_sum) / num;
        float dv = vv - 6.0f;
        if (fabsf(dv) > 4.0f) loss += 10.0f * dv * dv;
        out[0] = loss;
        // atomicInc already wrapped g_ticket to 0 for the next graph replay.
    }
}

extern "C" void kernel_launch(void* const* d_in, const int* in_sizes, int n_in,
                              void* d_out, int out_size)
{
    const float* lat    = (const float*)d_in[0];
    const float* lon    = (const float*)d_in[1];
    const float* v      = (const float*)d_in[2];
    const float* st_lat = (const float*)d_in[3];
    const float* st_lon = (const float*)d_in[4];
    const float* times  = (const float*)d_in[5];
    float* out = (float*)d_out;
    int n = in_sizes[3];  // station count

    int nblocks = (n + 31) / 32;
    if (nblocks > MAX_BLOCKS) nblocks = MAX_BLOCKS;  // n <= 16384 per scratch
    find_loc_warp<<<nblocks, 32>>>(lat, lon, v, st_lat, st_lon, times,
                                   out, n, nblocks);
}

// round 10
// speedup vs baseline: 1.0543x; 1.0543x over previous
#include <cuda_runtime.h>
#include <cuda_bf16.h>

// loss = [pen_neg(v) + (N*sum(r^2) - (sum r)^2)] / (N(N-1)/2) + pen_range(v)
// r_i = haversine(st_i, q) - v*t_i, DEG = 3.14/180 (sic).
//
// 128 blocks x 32 threads (single wave on 148 SMs), 2 stations/thread,
// zero smem/barriers, poly trig (one MUFU sqrt per station), deterministic
// fixed-point int64 atomic accumulation, last-ticket warp finalizes.

#define NBLOCKS 128
#define FXSCALE 1048576.0f   // 2^20

__device__ unsigned long long g_acc_s1 = 0ULL;
__device__ unsigned long long g_acc_s2 = 0ULL;
__device__ unsigned int g_ticket = 0;

__global__ void __launch_bounds__(32)
find_loc_warp(const float* __restrict__ lat,
              const float* __restrict__ lon,
              const float* __restrict__ v,
              const float* __restrict__ st_lat,
              const float* __restrict__ st_lon,
              const float* __restrict__ times,
              float* __restrict__ out,
              int n)
{
    const float DEG = 3.14f / 180.0f;
    const float R   = 6373.0f;
    const float C16 = 1.0f / 6.0f;

    const float la2 = lat[0] * DEG;
    const float lo2 = lon[0] * DEG;
    const float vv  = v[0];
    const float cos_la2 = __cosf(la2);
    const float sin_la2 = __sinf(la2);

    int lane = threadIdx.x;
    int base = blockIdx.x * 32 + lane;
    const int stride = NBLOCKS * 32;

    float s1 = 0.0f, s2 = 0.0f;
    #pragma unroll 2
    for (int i = base; i < n; i += stride) {
        float la1 = st_lat[i] * DEG;
        float lo1 = st_lon[i] * DEG;
        float dla = la2 - la1;            // |dla| <~ 0.05 rad
        float dlo = lo2 - lo1;

        // sin(x) ~= x - x^3/6 (rel err < 1e-8 at these magnitudes)
        float h = 0.5f * dla;
        float sdla = h * (1.0f - h * h * C16);
        float g = 0.5f * dlo;
        float sdlo = g * (1.0f - g * g * C16);

        // cos(la1) = cos(la2 + d), d tiny:
        float dd = la1 - la2;
        float dd2 = dd * dd;
        float cos_la1 = cos_la2 * (1.0f - 0.5f * dd2)
                      - sin_la2 * (dd * (1.0f - dd2 * C16));

        float a = sdla * sdla + cos_la1 * cos_la2 * (sdlo * sdlo);
        // 2*atan2(sqrt(a), sqrt(1-a)) = 2*asin(sqrt(a)), s small
        float s = __fsqrt_rn(a);
        float sq = s * s;
        float asin_s = s * (1.0f + sq * (C16 + sq * (3.0f / 40.0f)));
        float d = (2.0f * R) * asin_s;

        float r = d - vv * times[i];
        s1 += r;
        s2 += r * r;
    }

    // warp reduce (deterministic fixed order)
    #pragma unroll
    for (int off = 16; off > 0; off >>= 1) {
        s1 += __shfl_down_sync(0xFFFFFFFFu, s1, off);
        s2 += __shfl_down_sync(0xFFFFFFFFu, s2, off);
    }

    unsigned int tkt = 0;
    if (lane == 0) {
        // Fixed-point accumulate: integer adds commute -> deterministic.
        long long q1 = llrintf(s1 * FXSCALE);
        long long q2 = llrintf(s2 * FXSCALE);
        atomicAdd(&g_acc_s1, (unsigned long long)q1);
        atomicAdd(&g_acc_s2, (unsigned long long)q2);
        __threadfence();   // accumulators visible before ticket
        tkt = atomicInc(&g_ticket, NBLOCKS - 1);
    }
    tkt = __shfl_sync(0xFFFFFFFFu, tkt, 0);
    if (tkt != NBLOCKS - 1) return;

    if (lane == 0) {
        __threadfence();   // acquire accumulators
        long long q1 = (long long)*(volatile unsigned long long*)&g_acc_s1;
        long long q2 = (long long)*(volatile unsigned long long*)&g_acc_s2;
        float S1 = (float)((double)q1 * (1.0 / (double)FXSCALE));
        float S2 = (float)((double)q2 * (1.0 / (double)FXSCALE));

        float fn = (float)n;
        // sum_{i<j} (r_j - r_i)^2 = N*sum(r^2) - (sum r)^2
        float pair_sum = fn * S2 - S1 * S1;
        float pen_neg = (vv < 0.0f) ? (-vv * 10.0f) : 0.0f;
        float num = fn * (fn - 1.0f) * 0.5f;
        float loss = (pen_neg + pair_sum) / num;
        float dv = vv - 6.0f;
        if (fabsf(dv) > 4.0f) loss += 10.0f * dv * dv;
        out[0] = loss;

        // Reset accumulators for the next graph replay (ticket self-wraps).
        g_acc_s1 = 0ULL;
        g_acc_s2 = 0ULL;
        __threadfence();
    }
}

extern "C" void kernel_launch(void* const* d_in, const int* in_sizes, int n_in,
                              void* d_out, int out_size)
{
    const float* lat    = (const float*)d_in[0];
    const float* lon    = (const float*)d_in[1];
    const float* v      = (const float*)d_in[2];
    const float* st_lat = (const float*)d_in[3];
    const float* st_lon = (const float*)d_in[4];
    const float* times  = (const float*)d_in[5];
    float* out = (float*)d_out;
    int n = in_sizes[3];  // station count

    find_loc_warp<<<NBLOCKS, 32>>>(lat, lon, v, st_lat, st_lon, times, out, n);
}